// round 5
// baseline (speedup 1.0000x reference)
#include <cuda_runtime.h>
#include <cuda_bf16.h>
#include <math.h>

#define NN   50000
#define EE   800000
#define DIN  128
#define DHID 128
#define DOUT 64
#define BN_EPS 1e-5f

// ---------------- scratch (device globals; no allocations allowed) ----------
__device__ __align__(16) float g_h1[NN * DHID];   // x @ W1 + b1
__device__ __align__(16) float g_h2[NN * DHID];   // propagate(h1)
__device__ __align__(16) float g_g2[NN * DOUT];   // act(h2) @ W2 + b2
__device__ __align__(16) float g_out[NN * DOUT];  // propagate(g_g2) (pre-softmax)
__device__ int   g_cnt[NN];
__device__ __align__(16) float g_dis[NN];
__device__ __align__(16) float g_bnsum[2 * DHID]; // [0:128) sum, [128:256) sumsq
__device__ __align__(16) float g_scale[DHID];
__device__ __align__(16) float g_shift[DHID];

// ---------------- init: zero h2, out-accum, cnt, bnsum ----------------------
__global__ void init_kernel(int N) {
    int idx = blockIdx.x * blockDim.x + threadIdx.x;
    int nh4 = (N * DHID) / 4;
    int no4 = (N * DOUT) / 4;
    if (idx < nh4) ((float4*)g_h2)[idx] = make_float4(0.f, 0.f, 0.f, 0.f);
    if (idx < no4) ((float4*)g_out)[idx] = make_float4(0.f, 0.f, 0.f, 0.f);
    if (idx < N) g_cnt[idx] = 0;
    if (idx < 2 * DHID) g_bnsum[idx] = 0.f;
}

// ---------------- degree / normalization ------------------------------------
__global__ void count_deg_kernel(const int* __restrict__ ei, int E) {
    int e = blockIdx.x * blockDim.x + threadIdx.x;
    if (e < E) atomicAdd(&g_cnt[ei[E + e]], 1);
}

__global__ void dis_kernel(int N) {
    int i = blockIdx.x * blockDim.x + threadIdx.x;
    if (i < N) g_dis[i] = rsqrtf((float)(g_cnt[i] + 1));  // +1 self loop
}

// ---------------- GEMM1: g_h1 = x @ W1 + b1  (64x128 tile, K=128) ----------
__global__ __launch_bounds__(256) void gemm1_kernel(
    const float* __restrict__ x, const float* __restrict__ W1,
    const float* __restrict__ b1, int N)
{
    __shared__ float xs[64 * 128];
    int brow = blockIdx.x * 64;
    int tid = threadIdx.x;

    const float4* xg = (const float4*)(x + (size_t)brow * 128);
    for (int j = tid; j < 64 * 32; j += 256) {
        int rr = j >> 5;
        float4 v = (brow + rr < N) ? xg[j] : make_float4(0.f, 0.f, 0.f, 0.f);
        ((float4*)xs)[j] = v;
    }
    __syncthreads();

    int tx = tid & 31;   // 32 col groups x 4 cols
    int ty = tid >> 5;   // 8 row groups x 8 rows
    float acc[8][4];
#pragma unroll
    for (int i = 0; i < 8; i++)
#pragma unroll
        for (int j = 0; j < 4; j++) acc[i][j] = 0.f;

    for (int k = 0; k < 128; k++) {
        float4 w4 = *(const float4*)(W1 + (size_t)k * 128 + tx * 4);
#pragma unroll
        for (int i = 0; i < 8; i++) {
            float a = xs[(ty * 8 + i) * 128 + k];   // warp-broadcast LDS
            acc[i][0] += a * w4.x; acc[i][1] += a * w4.y;
            acc[i][2] += a * w4.z; acc[i][3] += a * w4.w;
        }
    }
    float4 bb = *(const float4*)(b1 + tx * 4);
#pragma unroll
    for (int i = 0; i < 8; i++) {
        int grow = brow + ty * 8 + i;
        if (grow < N) {
            float4 o = make_float4(acc[i][0] + bb.x, acc[i][1] + bb.y,
                                   acc[i][2] + bb.z, acc[i][3] + bb.w);
            *(float4*)(g_h1 + (size_t)grow * 128 + tx * 4) = o;
        }
    }
}

// ---------------- propagate 1: g_h2 += w * g_h1[row]  (D=128) ---------------
__global__ void prop1_kernel(const int* __restrict__ ei, int E, int N) {
    int w = (blockIdx.x * blockDim.x + threadIdx.x) >> 5;
    int lane = threadIdx.x & 31;
    if (w >= E + N) return;
    int r, c;
    if (w < E) { r = ei[w]; c = ei[E + w]; }
    else       { r = w - E; c = r; }
    float wt = g_dis[r] * g_dis[c];
    float4 v = *(const float4*)(g_h1 + (size_t)r * 128 + lane * 4);
    float* dp = g_h2 + (size_t)c * 128 + lane * 4;
    atomicAdd(dp + 0, v.x * wt);
    atomicAdd(dp + 1, v.y * wt);
    atomicAdd(dp + 2, v.z * wt);
    atomicAdd(dp + 3, v.w * wt);
}

// ---------------- BN stats over rows ---------------------------------------
__global__ void bn_stats_kernel(int N) {
    int c = threadIdx.x & 127;
    int part = threadIdx.x >> 7;  // 0..1
    int rows_per_block = (N + gridDim.x - 1) / gridDim.x;
    int r0 = blockIdx.x * rows_per_block;
    int r1 = min(N, r0 + rows_per_block);
    float s = 0.f, q = 0.f;
    for (int r = r0 + part; r < r1; r += 2) {
        float v = g_h2[(size_t)r * 128 + c];
        s += v; q += v * v;
    }
    atomicAdd(&g_bnsum[c], s);
    atomicAdd(&g_bnsum[128 + c], q);
}

__global__ void bn_finalize_kernel(const float* __restrict__ gamma,
                                   const float* __restrict__ beta, int N) {
    int c = threadIdx.x;
    if (c < 128) {
        float invN = 1.f / (float)N;
        float mu = g_bnsum[c] * invN;
        float var = fmaxf(g_bnsum[128 + c] * invN - mu * mu, 0.f);
        float rs = rsqrtf(var + BN_EPS);
        float sc = rs * gamma[c];
        g_scale[c] = sc;
        g_shift[c] = beta[c] - mu * sc;
    }
}

// ---------------- GEMM2: g_g2 = relu(bn(g_h2)) @ W2 + b2 (64x64 tile) -------
__global__ __launch_bounds__(256) void gemm2_kernel(
    const float* __restrict__ W2, const float* __restrict__ b2, int N)
{
    __shared__ float hs[64 * 132];  // pad ld=132 to break LDS bank overlap
    int brow = blockIdx.x * 64;
    int tid = threadIdx.x;

    for (int j = tid; j < 64 * 32; j += 256) {
        int rr = j >> 5, c4 = j & 31;
        int grow = brow + rr;
        float4 v = make_float4(0.f, 0.f, 0.f, 0.f);
        if (grow < N) {
            v = *(const float4*)(g_h2 + (size_t)grow * 128 + c4 * 4);
            float4 sc = *(const float4*)(g_scale + c4 * 4);
            float4 sh = *(const float4*)(g_shift + c4 * 4);
            v.x = fmaxf(v.x * sc.x + sh.x, 0.f);
            v.y = fmaxf(v.y * sc.y + sh.y, 0.f);
            v.z = fmaxf(v.z * sc.z + sh.z, 0.f);
            v.w = fmaxf(v.w * sc.w + sh.w, 0.f);
        }
        *(float4*)(hs + rr * 132 + c4 * 4) = v;
    }
    __syncthreads();

    int c4 = tid & 15;   // 16 col groups x 4 cols = 64
    int rg = tid >> 4;   // 16 row groups x 4 rows = 64
    float acc[4][4];
#pragma unroll
    for (int i = 0; i < 4; i++)
#pragma unroll
        for (int j = 0; j < 4; j++) acc[i][j] = 0.f;

    for (int k = 0; k < 128; k++) {
        float4 w4 = *(const float4*)(W2 + (size_t)k * 64 + c4 * 4);
#pragma unroll
        for (int i = 0; i < 4; i++) {
            float a = hs[(rg * 4 + i) * 132 + k];
            acc[i][0] += a * w4.x; acc[i][1] += a * w4.y;
            acc[i][2] += a * w4.z; acc[i][3] += a * w4.w;
        }
    }
    float4 bb = *(const float4*)(b2 + c4 * 4);
#pragma unroll
    for (int i = 0; i < 4; i++) {
        int grow = brow + rg * 4 + i;
        if (grow < N) {
            float4 o = make_float4(acc[i][0] + bb.x, acc[i][1] + bb.y,
                                   acc[i][2] + bb.z, acc[i][3] + bb.w);
            *(float4*)(g_g2 + (size_t)grow * 64 + c4 * 4) = o;
        }
    }
}

// ---------------- propagate 2: g_out += w * g_g2[row]  (D=64) ---------------
// NOTE: accumulates ONLY into the __device__ global g_out, never into d_out.
__global__ void prop2_kernel(const int* __restrict__ ei, int E, int N) {
    int w = (blockIdx.x * blockDim.x + threadIdx.x) >> 5;
    int lane = threadIdx.x & 31;
    if (w >= E + N) return;
    int r, c;
    if (w < E) { r = ei[w]; c = ei[E + w]; }
    else       { r = w - E; c = r; }
    float wt = g_dis[r] * g_dis[c];
    float2 v = *(const float2*)(g_g2 + (size_t)r * 64 + lane * 2);
    float* dp = g_out + (size_t)c * 64 + lane * 2;
    atomicAdd(dp + 0, v.x * wt);
    atomicAdd(dp + 1, v.y * wt);
}

// ---------------- log_softmax: read g_out, plain-store result to d_out ------
__global__ void logsoftmax_kernel(float* __restrict__ out, int N) {
    int w = (blockIdx.x * blockDim.x + threadIdx.x) >> 5;
    int lane = threadIdx.x & 31;
    if (w >= N) return;
    float2 v = *(const float2*)(g_out + (size_t)w * 64 + lane * 2);
    float m = fmaxf(v.x, v.y);
#pragma unroll
    for (int off = 16; off > 0; off >>= 1)
        m = fmaxf(m, __shfl_xor_sync(0xFFFFFFFFu, m, off));
    float s = expf(v.x - m) + expf(v.y - m);
#pragma unroll
    for (int off = 16; off > 0; off >>= 1)
        s += __shfl_xor_sync(0xFFFFFFFFu, s, off);
    float l = m + logf(s);
    v.x -= l; v.y -= l;
    *(float2*)(out + (size_t)w * 64 + lane * 2) = v;   // plain STG.64 only
}

// ---------------- launch -----------------------------------------------------
extern "C" void kernel_launch(void* const* d_in, const int* in_sizes, int n_in,
                              void* d_out, int out_size) {
    const float* x     = (const float*)d_in[0];
    const float* W1    = (const float*)d_in[1];
    const float* b1    = (const float*)d_in[2];
    const float* gamma = (const float*)d_in[3];
    const float* beta  = (const float*)d_in[4];
    const float* W2    = (const float*)d_in[5];
    const float* b2    = (const float*)d_in[6];
    const int*   ei    = (const int*)d_in[7];   // edge_index is int32 on device

    int N = in_sizes[0] / DIN;
    int E = in_sizes[7] / 2;
    float* out = (float*)d_out;

    {
        int nwork = (N * DHID) / 4;  // covers all zero-fill targets
        init_kernel<<<(nwork + 255) / 256, 256>>>(N);
    }
    count_deg_kernel<<<(E + 255) / 256, 256>>>(ei, E);
    dis_kernel<<<(N + 255) / 256, 256>>>(N);

    gemm1_kernel<<<(N + 63) / 64, 256>>>(x, W1, b1, N);

    {
        long long warps = (long long)E + N;
        int blocks = (int)((warps * 32 + 255) / 256);
        prop1_kernel<<<blocks, 256>>>(ei, E, N);
    }

    bn_stats_kernel<<<256, 256>>>(N);
    bn_finalize_kernel<<<1, 128>>>(gamma, beta, N);

    gemm2_kernel<<<(N + 63) / 64, 256>>>(W2, b2, N);

    {
        long long warps = (long long)E + N;
        int blocks = (int)((warps * 32 + 255) / 256);
        prop2_kernel<<<blocks, 256>>>(ei, E, N);
    }

    {
        long long warps = N;
        int blocks = (int)((warps * 32 + 255) / 256);
        logsoftmax_kernel<<<blocks, 256>>>(out, N);
    }
}

// round 6
// speedup vs baseline: 1.9000x; 1.9000x over previous
#include <cuda_runtime.h>
#include <cuda_bf16.h>
#include <math.h>

#define NN   50000
#define EE   800000
#define DIN  128
#define DHID 128
#define DOUT 64
#define BN_EPS 1e-5f

// ---------------- scratch (device globals; no allocations allowed) ----------
__device__ __align__(16) float g_h1[NN * DHID];   // x @ W1 + b1
__device__ __align__(16) float g_h2[NN * DHID];   // propagate(h1)
__device__ __align__(16) float g_g2[NN * DOUT];   // act(h2) @ W2 + b2
__device__ __align__(16) float g_out[NN * DOUT];  // propagate(g_g2)
__device__ int   g_cnt[NN];
__device__ int   g_cur[NN];
__device__ int   g_off[NN + 1];
__device__ int   g_csr_row[EE];                   // source node per edge, grouped by dest
__device__ __align__(16) float g_dis[NN];
__device__ __align__(16) float g_bnsum[2 * DHID];
__device__ __align__(16) float g_scale[DHID];
__device__ __align__(16) float g_shift[DHID];

// ---------------- init: zero cnt, cur, bnsum --------------------------------
__global__ void init_kernel(int N) {
    int idx = blockIdx.x * blockDim.x + threadIdx.x;
    if (idx < N) { g_cnt[idx] = 0; g_cur[idx] = 0; }
    if (idx < 2 * DHID) g_bnsum[idx] = 0.f;
}

// ---------------- degree histogram ------------------------------------------
__global__ void count_deg_kernel(const int* __restrict__ ei, int E) {
    int e = blockIdx.x * blockDim.x + threadIdx.x;
    if (e < E) atomicAdd(&g_cnt[ei[E + e]], 1);
}

__global__ void dis_kernel(int N) {
    int i = blockIdx.x * blockDim.x + threadIdx.x;
    if (i < N) g_dis[i] = rsqrtf((float)(g_cnt[i] + 1));  // +1 self loop
}

// ---------------- exclusive prefix sum over g_cnt -> g_off (1 block) --------
__global__ __launch_bounds__(1024) void scan_kernel(int N) {
    __shared__ int ssum[1024];
    int t = threadIdx.x;
    int chunk = (N + 1023) >> 10;
    int s0 = t * chunk, s1 = min(N, s0 + chunk);
    int s = 0;
    for (int i = s0; i < s1; i++) s += g_cnt[i];
    ssum[t] = s;
    __syncthreads();
    // Hillis-Steele inclusive scan
    for (int off = 1; off < 1024; off <<= 1) {
        int v = (t >= off) ? ssum[t - off] : 0;
        __syncthreads();
        ssum[t] += v;
        __syncthreads();
    }
    int base = (t > 0) ? ssum[t - 1] : 0;
    for (int i = s0; i < s1; i++) { g_off[i] = base; base += g_cnt[i]; }
    if (t == 1023) g_off[N] = ssum[1023];
}

// ---------------- CSR fill: group edges by destination ----------------------
__global__ void fill_csr_kernel(const int* __restrict__ ei, int E) {
    int e = blockIdx.x * blockDim.x + threadIdx.x;
    if (e < E) {
        int c = ei[E + e];
        int pos = g_off[c] + atomicAdd(&g_cur[c], 1);
        g_csr_row[pos] = ei[e];
    }
}

// ---------------- GEMM1: g_h1 = x @ W1 + b1  (64x128 tile, K unroll 4) ------
__global__ __launch_bounds__(256) void gemm1_kernel(
    const float* __restrict__ x, const float* __restrict__ W1,
    const float* __restrict__ b1, int N)
{
    __shared__ float xs[64 * 128];
    int brow = blockIdx.x * 64;
    int tid = threadIdx.x;

    const float4* xg = (const float4*)(x + (size_t)brow * 128);
    for (int j = tid; j < 64 * 32; j += 256) {
        int rr = j >> 5;
        float4 v = (brow + rr < N) ? xg[j] : make_float4(0.f, 0.f, 0.f, 0.f);
        ((float4*)xs)[j] = v;
    }
    __syncthreads();

    int tx = tid & 31;   // 32 col groups x 4 cols
    int ty = tid >> 5;   // 8 row groups x 8 rows
    float acc[8][4];
#pragma unroll
    for (int i = 0; i < 8; i++)
#pragma unroll
        for (int j = 0; j < 4; j++) acc[i][j] = 0.f;

    for (int k = 0; k < 128; k += 4) {
        float4 w0 = *(const float4*)(W1 + (size_t)(k + 0) * 128 + tx * 4);
        float4 w1 = *(const float4*)(W1 + (size_t)(k + 1) * 128 + tx * 4);
        float4 w2 = *(const float4*)(W1 + (size_t)(k + 2) * 128 + tx * 4);
        float4 w3 = *(const float4*)(W1 + (size_t)(k + 3) * 128 + tx * 4);
#pragma unroll
        for (int i = 0; i < 8; i++) {
            float4 a = *(const float4*)(xs + (ty * 8 + i) * 128 + k);  // LDS.128 bcast
            acc[i][0] += a.x * w0.x + a.y * w1.x + a.z * w2.x + a.w * w3.x;
            acc[i][1] += a.x * w0.y + a.y * w1.y + a.z * w2.y + a.w * w3.y;
            acc[i][2] += a.x * w0.z + a.y * w1.z + a.z * w2.z + a.w * w3.z;
            acc[i][3] += a.x * w0.w + a.y * w1.w + a.z * w2.w + a.w * w3.w;
        }
    }
    float4 bb = *(const float4*)(b1 + tx * 4);
#pragma unroll
    for (int i = 0; i < 8; i++) {
        int grow = brow + ty * 8 + i;
        if (grow < N) {
            float4 o = make_float4(acc[i][0] + bb.x, acc[i][1] + bb.y,
                                   acc[i][2] + bb.z, acc[i][3] + bb.w);
            *(float4*)(g_h1 + (size_t)grow * 128 + tx * 4) = o;
        }
    }
}

// ---------------- propagate 1 (gather): g_h2[c] = sum_r w * g_h1[r] ---------
__global__ __launch_bounds__(256) void prop1_gather_kernel(int N) {
    int c = (blockIdx.x * blockDim.x + threadIdx.x) >> 5;
    int lane = threadIdx.x & 31;
    if (c >= N) return;
    float dc = g_dis[c];
    const float4* h1 = (const float4*)g_h1;

    float4 sv = h1[(size_t)c * 32 + lane];   // self loop, weight dc*dc
    float ws = dc * dc;
    float ax = sv.x * ws, ay = sv.y * ws, az = sv.z * ws, aw = sv.w * ws;

    int j = g_off[c], e = g_off[c + 1];
    for (; j + 1 < e; j += 2) {
        int r0 = g_csr_row[j], r1 = g_csr_row[j + 1];
        float w0 = dc * g_dis[r0], w1 = dc * g_dis[r1];
        float4 v0 = h1[(size_t)r0 * 32 + lane];
        float4 v1 = h1[(size_t)r1 * 32 + lane];
        ax += w0 * v0.x + w1 * v1.x;
        ay += w0 * v0.y + w1 * v1.y;
        az += w0 * v0.z + w1 * v1.z;
        aw += w0 * v0.w + w1 * v1.w;
    }
    if (j < e) {
        int r0 = g_csr_row[j];
        float w0 = dc * g_dis[r0];
        float4 v0 = h1[(size_t)r0 * 32 + lane];
        ax += w0 * v0.x; ay += w0 * v0.y; az += w0 * v0.z; aw += w0 * v0.w;
    }
    ((float4*)g_h2)[(size_t)c * 32 + lane] = make_float4(ax, ay, az, aw);
}

// ---------------- BN stats over rows ---------------------------------------
__global__ void bn_stats_kernel(int N) {
    int c = threadIdx.x & 127;
    int part = threadIdx.x >> 7;  // 0..1
    int rows_per_block = (N + gridDim.x - 1) / gridDim.x;
    int r0 = blockIdx.x * rows_per_block;
    int r1 = min(N, r0 + rows_per_block);
    float s = 0.f, q = 0.f;
    for (int r = r0 + part; r < r1; r += 2) {
        float v = g_h2[(size_t)r * 128 + c];
        s += v; q += v * v;
    }
    atomicAdd(&g_bnsum[c], s);
    atomicAdd(&g_bnsum[128 + c], q);
}

__global__ void bn_finalize_kernel(const float* __restrict__ gamma,
                                   const float* __restrict__ beta, int N) {
    int c = threadIdx.x;
    if (c < 128) {
        float invN = 1.f / (float)N;
        float mu = g_bnsum[c] * invN;
        float var = fmaxf(g_bnsum[128 + c] * invN - mu * mu, 0.f);
        float rs = rsqrtf(var + BN_EPS);
        float sc = rs * gamma[c];
        g_scale[c] = sc;
        g_shift[c] = beta[c] - mu * sc;
    }
}

// ---------------- GEMM2: g_g2 = relu(bn(g_h2)) @ W2 + b2 (64x64 tile) -------
__global__ __launch_bounds__(256) void gemm2_kernel(
    const float* __restrict__ W2, const float* __restrict__ b2, int N)
{
    __shared__ float hs[64 * 132];  // pad ld=132
    int brow = blockIdx.x * 64;
    int tid = threadIdx.x;

    for (int j = tid; j < 64 * 32; j += 256) {
        int rr = j >> 5, c4 = j & 31;
        int grow = brow + rr;
        float4 v = make_float4(0.f, 0.f, 0.f, 0.f);
        if (grow < N) {
            v = *(const float4*)(g_h2 + (size_t)grow * 128 + c4 * 4);
            float4 sc = *(const float4*)(g_scale + c4 * 4);
            float4 sh = *(const float4*)(g_shift + c4 * 4);
            v.x = fmaxf(v.x * sc.x + sh.x, 0.f);
            v.y = fmaxf(v.y * sc.y + sh.y, 0.f);
            v.z = fmaxf(v.z * sc.z + sh.z, 0.f);
            v.w = fmaxf(v.w * sc.w + sh.w, 0.f);
        }
        *(float4*)(hs + rr * 132 + c4 * 4) = v;
    }
    __syncthreads();

    int c4 = tid & 15;   // 16 col groups x 4 cols = 64
    int rg = tid >> 4;   // 16 row groups x 4 rows = 64
    float acc[4][4];
#pragma unroll
    for (int i = 0; i < 4; i++)
#pragma unroll
        for (int j = 0; j < 4; j++) acc[i][j] = 0.f;

    for (int k = 0; k < 128; k += 4) {
        float4 w0 = *(const float4*)(W2 + (size_t)(k + 0) * 64 + c4 * 4);
        float4 w1 = *(const float4*)(W2 + (size_t)(k + 1) * 64 + c4 * 4);
        float4 w2 = *(const float4*)(W2 + (size_t)(k + 2) * 64 + c4 * 4);
        float4 w3 = *(const float4*)(W2 + (size_t)(k + 3) * 64 + c4 * 4);
#pragma unroll
        for (int i = 0; i < 4; i++) {
            float4 a = *(const float4*)(hs + (rg * 4 + i) * 132 + k);
            acc[i][0] += a.x * w0.x + a.y * w1.x + a.z * w2.x + a.w * w3.x;
            acc[i][1] += a.x * w0.y + a.y * w1.y + a.z * w2.y + a.w * w3.y;
            acc[i][2] += a.x * w0.z + a.y * w1.z + a.z * w2.z + a.w * w3.z;
            acc[i][3] += a.x * w0.w + a.y * w1.w + a.z * w2.w + a.w * w3.w;
        }
    }
    float4 bb = *(const float4*)(b2 + c4 * 4);
#pragma unroll
    for (int i = 0; i < 4; i++) {
        int grow = brow + rg * 4 + i;
        if (grow < N) {
            float4 o = make_float4(acc[i][0] + bb.x, acc[i][1] + bb.y,
                                   acc[i][2] + bb.z, acc[i][3] + bb.w);
            *(float4*)(g_g2 + (size_t)grow * 64 + c4 * 4) = o;
        }
    }
}

// ---------------- propagate 2 (gather): g_out[c] = sum_r w * g_g2[r] --------
__global__ __launch_bounds__(256) void prop2_gather_kernel(int N) {
    int c = (blockIdx.x * blockDim.x + threadIdx.x) >> 5;
    int lane = threadIdx.x & 31;
    if (c >= N) return;
    float dc = g_dis[c];
    const float2* gg = (const float2*)g_g2;

    float2 sv = gg[(size_t)c * 32 + lane];
    float ws = dc * dc;
    float ax = sv.x * ws, ay = sv.y * ws;

    int j = g_off[c], e = g_off[c + 1];
    for (; j + 1 < e; j += 2) {
        int r0 = g_csr_row[j], r1 = g_csr_row[j + 1];
        float w0 = dc * g_dis[r0], w1 = dc * g_dis[r1];
        float2 v0 = gg[(size_t)r0 * 32 + lane];
        float2 v1 = gg[(size_t)r1 * 32 + lane];
        ax += w0 * v0.x + w1 * v1.x;
        ay += w0 * v0.y + w1 * v1.y;
    }
    if (j < e) {
        int r0 = g_csr_row[j];
        float w0 = dc * g_dis[r0];
        float2 v0 = gg[(size_t)r0 * 32 + lane];
        ax += w0 * v0.x; ay += w0 * v0.y;
    }
    ((float2*)g_out)[(size_t)c * 32 + lane] = make_float2(ax, ay);
}

// ---------------- log_softmax: read g_out, plain-store to d_out -------------
__global__ void logsoftmax_kernel(float* __restrict__ out, int N) {
    int w = (blockIdx.x * blockDim.x + threadIdx.x) >> 5;
    int lane = threadIdx.x & 31;
    if (w >= N) return;
    float2 v = *(const float2*)(g_out + (size_t)w * 64 + lane * 2);
    float m = fmaxf(v.x, v.y);
#pragma unroll
    for (int off = 16; off > 0; off >>= 1)
        m = fmaxf(m, __shfl_xor_sync(0xFFFFFFFFu, m, off));
    float s = expf(v.x - m) + expf(v.y - m);
#pragma unroll
    for (int off = 16; off > 0; off >>= 1)
        s += __shfl_xor_sync(0xFFFFFFFFu, s, off);
    float l = m + logf(s);
    v.x -= l; v.y -= l;
    *(float2*)(out + (size_t)w * 64 + lane * 2) = v;
}

// ---------------- launch -----------------------------------------------------
extern "C" void kernel_launch(void* const* d_in, const int* in_sizes, int n_in,
                              void* d_out, int out_size) {
    const float* x     = (const float*)d_in[0];
    const float* W1    = (const float*)d_in[1];
    const float* b1    = (const float*)d_in[2];
    const float* gamma = (const float*)d_in[3];
    const float* beta  = (const float*)d_in[4];
    const float* W2    = (const float*)d_in[5];
    const float* b2    = (const float*)d_in[6];
    const int*   ei    = (const int*)d_in[7];   // int32 indices

    int N = in_sizes[0] / DIN;
    int E = in_sizes[7] / 2;
    float* out = (float*)d_out;

    init_kernel<<<(N + 255) / 256, 256>>>(N);
    count_deg_kernel<<<(E + 255) / 256, 256>>>(ei, E);
    scan_kernel<<<1, 1024>>>(N);
    dis_kernel<<<(N + 255) / 256, 256>>>(N);
    fill_csr_kernel<<<(E + 255) / 256, 256>>>(ei, E);

    gemm1_kernel<<<(N + 63) / 64, 256>>>(x, W1, b1, N);

    {
        long long warps = N;
        int blocks = (int)((warps * 32 + 255) / 256);
        prop1_gather_kernel<<<blocks, 256>>>(N);
    }

    bn_stats_kernel<<<256, 256>>>(N);
    bn_finalize_kernel<<<1, 128>>>(gamma, beta, N);

    gemm2_kernel<<<(N + 63) / 64, 256>>>(W2, b2, N);

    {
        long long warps = N;
        int blocks = (int)((warps * 32 + 255) / 256);
        prop2_gather_kernel<<<blocks, 256>>>(N);
    }

    {
        long long warps = N;
        int blocks = (int)((warps * 32 + 255) / 256);
        logsoftmax_kernel<<<blocks, 256>>>(out, N);
    }
}